// round 10
// baseline (speedup 1.0000x reference)
#include <cuda_runtime.h>
#include <cuda_bf16.h>
#include <cstdint>

// IndRNN (sm_103a, baseline-PTX -> warp mma.sync tf32):
//   proj = x @ W + b : single-pass TF32 HMMA GEMM (93% of HMMA.1688 ceiling).
//   scan: h_t = relu(proj_t + h_{t-1}*clip(u,0,1)); float2 chains (2 per thread),
//         depth-16 double-buffered -> half the LSU ops/byte (scan was LSU-bound).

#define M_DIM 32768
#define K_DIM 256
#define U_DIM 512

// ---------------------------------------------------------------------------
__device__ __forceinline__ uint32_t smem_u32(const void* p) {
    uint32_t a;
    asm("{ .reg .u64 t; cvta.to.shared.u64 t, %1; cvt.u32.u64 %0, t; }" : "=r"(a) : "l"(p));
    return a;
}
__device__ __forceinline__ void cp_async16(uint32_t saddr, const void* gptr) {
    asm volatile("cp.async.cg.shared.global [%0], [%1], 16;" :: "r"(saddr), "l"(gptr));
}
__device__ __forceinline__ void cp_commit() { asm volatile("cp.async.commit_group;"); }
__device__ __forceinline__ void cp_wait0() { asm volatile("cp.async.wait_group 0;"); }

__device__ __forceinline__ uint32_t f2tf32(float f) {
    uint32_t r;
    asm("cvt.rna.tf32.f32 %0, %1;" : "=r"(r) : "f"(f));
    return r;
}
__device__ __forceinline__ void mma16888(float* c, const uint32_t* a, uint32_t b0, uint32_t b1) {
    asm volatile(
        "mma.sync.aligned.m16n8k8.row.col.f32.tf32.tf32.f32 "
        "{%0,%1,%2,%3}, {%4,%5,%6,%7}, {%8,%9}, {%0,%1,%2,%3};"
        : "+f"(c[0]), "+f"(c[1]), "+f"(c[2]), "+f"(c[3])
        : "r"(a[0]), "r"(a[1]), "r"(a[2]), "r"(a[3]), "r"(b0), "r"(b1));
}

// ---------------------------------------------------------------------------
// TF32 HMMA GEMM: CTA 128(M)x128(N), BK=32, 8 warps (4M x 2N), warp 32x64.
// A smem: 128 rows(m) x 32 f32(k), pitch 144B. B smem: 32 rows(k) x 128 f32(n),
// pitch 544B (banks 8*tig+g, conflict-free). Double-buffered.
// A: LDG fp32 -> cvt.rna.tf32 -> STS (one stage ahead). B: cp.async native W.
// ---------------------------------------------------------------------------
#define APITCH 144
#define BPITCH 544
#define PART_A (128 * APITCH)
#define PART_B (32 * BPITCH)
#define STAGE_BYTES (PART_A + PART_B)
#define GEMM_SMEM (2 * STAGE_BYTES)

__global__ __launch_bounds__(256) void indrnn_gemm_tf32(
    const float* __restrict__ X, const float* __restrict__ W,
    const float* __restrict__ bias, float* __restrict__ C)
{
    extern __shared__ __align__(16) char smem[];
    const uint32_t sbase = smem_u32(smem);

    const int tid = threadIdx.x;
    const int lane = tid & 31, warp = tid >> 5;
    const int wm = (warp & 3) * 32;
    const int wn = (warp >> 2) * 64;
    const int g = lane >> 2, tig = lane & 3;

    const int n0 = blockIdx.x * 128;
    const int m0 = blockIdx.y * 128;

    int ar[4], ac4[4];
#pragma unroll
    for (int j = 0; j < 4; j++) {
        int q = tid + j * 256;
        ar[j] = q >> 3;
        ac4[j] = q & 7;
    }

    auto ldgA = [&](int k0, float4* regs) {
#pragma unroll
        for (int j = 0; j < 4; j++)
            regs[j] = *(const float4*)&X[(size_t)(m0 + ar[j]) * K_DIM + k0 + ac4[j] * 4];
    };
    auto stsA = [&](int buf, const float4* regs) {
        char* s0 = smem + buf * STAGE_BYTES;
#pragma unroll
        for (int j = 0; j < 4; j++) {
            uint4 t;
            t.x = f2tf32(regs[j].x);
            t.y = f2tf32(regs[j].y);
            t.z = f2tf32(regs[j].z);
            t.w = f2tf32(regs[j].w);
            *(uint4*)(s0 + ar[j] * APITCH + ac4[j] * 16) = t;
        }
    };
    auto cpB = [&](int buf, int k0) {
        const uint32_t s0 = sbase + buf * STAGE_BYTES + PART_A;
#pragma unroll
        for (int j = 0; j < 4; j++) {
            int c = tid + j * 256;
            int r = c >> 5, unit = c & 31;
            cp_async16(s0 + r * BPITCH + unit * 16,
                       W + (size_t)(k0 + r) * U_DIM + n0 + unit * 4);
        }
    };

    float acc[2][8][4];
#pragma unroll
    for (int ms = 0; ms < 2; ms++)
#pragma unroll
        for (int ns = 0; ns < 8; ns++)
#pragma unroll
            for (int i = 0; i < 4; i++) acc[ms][ns][i] = 0.0f;

    const int NKT = K_DIM / 32;  // 8
    float4 regs[4];

    ldgA(0, regs);
    cpB(0, 0);
    cp_commit();
    stsA(0, regs);
    ldgA(32, regs);
    cp_wait0();
    __syncthreads();

    for (int kt = 0; kt < NKT; kt++) {
        const int buf = kt & 1;

        if (kt + 1 < NKT) {
            stsA(buf ^ 1, regs);
            cpB(buf ^ 1, (kt + 1) * 32);
            cp_commit();
        }
        if (kt + 2 < NKT) ldgA((kt + 2) * 32, regs);

        const char* sA = smem + buf * STAGE_BYTES;
        const char* sB = sA + PART_A;

#pragma unroll
        for (int ks = 0; ks < 4; ks++) {
            const int cb = ks * 32 + tig * 4;
            uint32_t a[2][4];
#pragma unroll
            for (int ms = 0; ms < 2; ms++) {
                const int r = wm + ms * 16 + g;
                a[ms][0] = *(const uint32_t*)(sA + r * APITCH + cb);
                a[ms][1] = *(const uint32_t*)(sA + (r + 8) * APITCH + cb);
                a[ms][2] = *(const uint32_t*)(sA + r * APITCH + cb + 16);
                a[ms][3] = *(const uint32_t*)(sA + (r + 8) * APITCH + cb + 16);
            }
            const char* bn = sB + (ks * 8 + tig) * BPITCH + (wn + g) * 4;
#pragma unroll
            for (int ns = 0; ns < 8; ns++) {
                uint32_t b0 = f2tf32(*(const float*)(bn + ns * 32));
                uint32_t b1 = f2tf32(*(const float*)(bn + 4 * BPITCH + ns * 32));
#pragma unroll
                for (int ms = 0; ms < 2; ms++)
                    mma16888(acc[ms][ns], a[ms], b0, b1);
            }
        }
        if (kt + 1 < NKT) cp_wait0();
        __syncthreads();
    }

#pragma unroll
    for (int ns = 0; ns < 8; ns++) {
        const int n = n0 + wn + ns * 8 + 2 * tig;
        float2 bb = *(const float2*)(bias + n);
#pragma unroll
        for (int ms = 0; ms < 2; ms++) {
            const int m = m0 + wm + ms * 16 + g;
            float2 o0, o1;
            o0.x = acc[ms][ns][0] + bb.x;
            o0.y = acc[ms][ns][1] + bb.y;
            o1.x = acc[ms][ns][2] + bb.x;
            o1.y = acc[ms][ns][3] + bb.y;
            *(float2*)(C + (size_t)m * U_DIM + n) = o0;
            *(float2*)(C + (size_t)(m + 8) * U_DIM + n) = o1;
        }
    }
}

// ---------------------------------------------------------------------------
__global__ void indrnn_gemm_naive(
    const float* __restrict__ A, const float* __restrict__ Bw,
    const float* __restrict__ bias, float* __restrict__ Cc,
    int M, int N, int K)
{
    int idx = blockIdx.x * blockDim.x + threadIdx.x;
    if (idx >= M * N) return;
    int m = idx / N, n = idx % N;
    float s = bias[n];
    for (int k = 0; k < K; k++) s = fmaf(A[(size_t)m * K + k], Bw[(size_t)k * N + n], s);
    Cc[idx] = s;
}

// ---------------------------------------------------------------------------
// Scan v2: each thread owns TWO adjacent (b,u) chains (float2). Depth-16
// double-buffered (ping/pong reg arrays, no copy). Half the LSU ops per byte
// vs scalar; two independent fma chains per thread.
// Grid: (B*U/2) threads in 64-thread blocks -> covers all SMs.
// ---------------------------------------------------------------------------
__global__ __launch_bounds__(64) void indrnn_scan2(
    float* __restrict__ out, const float* __restrict__ h0,
    const float* __restrict__ u, int B, int T, int U)
{
    const int U2 = U >> 1;
    int idx = blockIdx.x * blockDim.x + threadIdx.x;
    if (idx >= B * U2) return;
    int b = idx / U2;
    int j2 = idx - b * U2;

    float2 uu = ((const float2*)u)[j2];
    float ucx = fminf(fmaxf(uu.x, 0.0f), 1.0f);
    float ucy = fminf(fmaxf(uu.y, 0.0f), 1.0f);
    float2 h = ((const float2*)h0)[(size_t)b * U2 + j2];

    float2* p = (float2*)out + (size_t)b * T * U2 + j2;
    const size_t st = (size_t)U2;

#define SCAN_PROC(buf, pw)                                     \
    do {                                                        \
        _Pragma("unroll")                                       \
        for (int i = 0; i < 16; i++) {                          \
            h.x = fmaxf(fmaf(h.x, ucx, (buf)[i].x), 0.0f);      \
            h.y = fmaxf(fmaf(h.y, ucy, (buf)[i].y), 0.0f);      \
            (pw)[i * st] = h;                                   \
        }                                                       \
    } while (0)

    if ((T & 31) == 0 && T >= 64) {
        float2 va[16], vb[16];
        const int NB = T / 16;             // even (T % 32 == 0)

#pragma unroll
        for (int i = 0; i < 16; i++) va[i] = __ldcs(p + i * st);

        for (int bI = 0; bI < NB; bI += 2) {
            float2* pa = p;                // batch bI
            float2* pb = p + 16 * st;      // batch bI+1
            if (bI + 1 < NB) {
#pragma unroll
                for (int i = 0; i < 16; i++) vb[i] = __ldcs(pb + i * st);
            }
            SCAN_PROC(va, pa);
            if (bI + 1 >= NB) break;
            if (bI + 2 < NB) {
                float2* pc = p + 32 * st;  // batch bI+2
#pragma unroll
                for (int i = 0; i < 16; i++) va[i] = __ldcs(pc + i * st);
            }
            SCAN_PROC(vb, pb);
            p += 32 * st;
        }
    } else {
        for (int t = 0; t < T; t++) {
            float2 v = __ldcs(p);
            h.x = fmaxf(fmaf(h.x, ucx, v.x), 0.0f);
            h.y = fmaxf(fmaf(h.y, ucy, v.y), 0.0f);
            *p = h;
            p += st;
        }
    }
#undef SCAN_PROC
}

// Scalar fallback for odd U (keeps correctness for any shape).
__global__ __launch_bounds__(128) void indrnn_scan1(
    float* __restrict__ out, const float* __restrict__ h0,
    const float* __restrict__ u, int B, int T, int U)
{
    int idx = blockIdx.x * blockDim.x + threadIdx.x;
    if (idx >= B * U) return;
    int b = idx / U;
    int j = idx - b * U;
    float uc = fminf(fmaxf(u[j], 0.0f), 1.0f);
    float h = h0[idx];
    float* p = out + (size_t)b * T * U + j;
    for (int t = 0; t < T; t++) {
        float v = __ldcg(p);
        h = fmaxf(fmaf(h, uc, v), 0.0f);
        *p = h;
        p += (size_t)U;
    }
}

// ---------------------------------------------------------------------------
extern "C" void kernel_launch(void* const* d_in, const int* in_sizes, int n_in,
                              void* d_out, int out_size)
{
    const float* x  = (const float*)d_in[0];
    const float* h0 = (const float*)d_in[1];
    const float* W  = (const float*)d_in[2];
    const float* u  = (const float*)d_in[3];
    const float* bb = (const float*)d_in[4];
    float* out = (float*)d_out;

    const int U = in_sizes[3];
    const int B = in_sizes[1] / U;
    const int D = in_sizes[2] / U;
    const int T = in_sizes[0] / (B * D);

    const int M = B * T;
    const int N = U;
    const int K = D;

    if (M == M_DIM && N == U_DIM && K == K_DIM) {
        cudaFuncSetAttribute(indrnn_gemm_tf32,
                             cudaFuncAttributeMaxDynamicSharedMemorySize, GEMM_SMEM);
        indrnn_gemm_tf32<<<dim3(N / 128, M / 128), 256, GEMM_SMEM>>>(x, W, bb, out);
    } else {
        int total = M * N;
        indrnn_gemm_naive<<<(total + 255) / 256, 256>>>(x, W, bb, out, M, N, K);
    }

    if ((U & 1) == 0) {
        int pairs = B * (U >> 1);
        indrnn_scan2<<<(pairs + 63) / 64, 64>>>(out, h0, u, B, T, U);
    } else {
        int chains = B * U;
        indrnn_scan1<<<(chains + 127) / 128, 128>>>(out, h0, u, B, T, U);
    }
}

// round 11
// speedup vs baseline: 1.0022x; 1.0022x over previous
#include <cuda_runtime.h>
#include <cuda_bf16.h>
#include <cstdint>

// IndRNN (sm_103a, baseline-PTX -> warp mma.sync tf32):
//   proj = x @ W + b : single-pass TF32 HMMA GEMM (93% of HMMA.1688 ceiling).
//   scan: float2 chains (2 per thread), depth-32 double-buffered ping-pong ->
//         4 MB chip-wide in flight (round-9 level) at half the LSU ops.

#define M_DIM 32768
#define K_DIM 256
#define U_DIM 512

// ---------------------------------------------------------------------------
__device__ __forceinline__ uint32_t smem_u32(const void* p) {
    uint32_t a;
    asm("{ .reg .u64 t; cvta.to.shared.u64 t, %1; cvt.u32.u64 %0, t; }" : "=r"(a) : "l"(p));
    return a;
}
__device__ __forceinline__ void cp_async16(uint32_t saddr, const void* gptr) {
    asm volatile("cp.async.cg.shared.global [%0], [%1], 16;" :: "r"(saddr), "l"(gptr));
}
__device__ __forceinline__ void cp_commit() { asm volatile("cp.async.commit_group;"); }
__device__ __forceinline__ void cp_wait0() { asm volatile("cp.async.wait_group 0;"); }

__device__ __forceinline__ uint32_t f2tf32(float f) {
    uint32_t r;
    asm("cvt.rna.tf32.f32 %0, %1;" : "=r"(r) : "f"(f));
    return r;
}
__device__ __forceinline__ void mma16888(float* c, const uint32_t* a, uint32_t b0, uint32_t b1) {
    asm volatile(
        "mma.sync.aligned.m16n8k8.row.col.f32.tf32.tf32.f32 "
        "{%0,%1,%2,%3}, {%4,%5,%6,%7}, {%8,%9}, {%0,%1,%2,%3};"
        : "+f"(c[0]), "+f"(c[1]), "+f"(c[2]), "+f"(c[3])
        : "r"(a[0]), "r"(a[1]), "r"(a[2]), "r"(a[3]), "r"(b0), "r"(b1));
}

// ---------------------------------------------------------------------------
// TF32 HMMA GEMM: CTA 128(M)x128(N), BK=32, 8 warps (4M x 2N), warp 32x64.
// A smem: 128 rows(m) x 32 f32(k), pitch 144B. B smem: 32 rows(k) x 128 f32(n),
// pitch 544B (banks 8*tig+g, conflict-free). Double-buffered.
// A: LDG fp32 -> cvt.rna.tf32 -> STS (one stage ahead). B: cp.async native W.
// ---------------------------------------------------------------------------
#define APITCH 144
#define BPITCH 544
#define PART_A (128 * APITCH)
#define PART_B (32 * BPITCH)
#define STAGE_BYTES (PART_A + PART_B)
#define GEMM_SMEM (2 * STAGE_BYTES)

__global__ __launch_bounds__(256) void indrnn_gemm_tf32(
    const float* __restrict__ X, const float* __restrict__ W,
    const float* __restrict__ bias, float* __restrict__ C)
{
    extern __shared__ __align__(16) char smem[];
    const uint32_t sbase = smem_u32(smem);

    const int tid = threadIdx.x;
    const int lane = tid & 31, warp = tid >> 5;
    const int wm = (warp & 3) * 32;
    const int wn = (warp >> 2) * 64;
    const int g = lane >> 2, tig = lane & 3;

    const int n0 = blockIdx.x * 128;
    const int m0 = blockIdx.y * 128;

    int ar[4], ac4[4];
#pragma unroll
    for (int j = 0; j < 4; j++) {
        int q = tid + j * 256;
        ar[j] = q >> 3;
        ac4[j] = q & 7;
    }

    auto ldgA = [&](int k0, float4* regs) {
#pragma unroll
        for (int j = 0; j < 4; j++)
            regs[j] = *(const float4*)&X[(size_t)(m0 + ar[j]) * K_DIM + k0 + ac4[j] * 4];
    };
    auto stsA = [&](int buf, const float4* regs) {
        char* s0 = smem + buf * STAGE_BYTES;
#pragma unroll
        for (int j = 0; j < 4; j++) {
            uint4 t;
            t.x = f2tf32(regs[j].x);
            t.y = f2tf32(regs[j].y);
            t.z = f2tf32(regs[j].z);
            t.w = f2tf32(regs[j].w);
            *(uint4*)(s0 + ar[j] * APITCH + ac4[j] * 16) = t;
        }
    };
    auto cpB = [&](int buf, int k0) {
        const uint32_t s0 = sbase + buf * STAGE_BYTES + PART_A;
#pragma unroll
        for (int j = 0; j < 4; j++) {
            int c = tid + j * 256;
            int r = c >> 5, unit = c & 31;
            cp_async16(s0 + r * BPITCH + unit * 16,
                       W + (size_t)(k0 + r) * U_DIM + n0 + unit * 4);
        }
    };

    float acc[2][8][4];
#pragma unroll
    for (int ms = 0; ms < 2; ms++)
#pragma unroll
        for (int ns = 0; ns < 8; ns++)
#pragma unroll
            for (int i = 0; i < 4; i++) acc[ms][ns][i] = 0.0f;

    const int NKT = K_DIM / 32;  // 8
    float4 regs[4];

    ldgA(0, regs);
    cpB(0, 0);
    cp_commit();
    stsA(0, regs);
    ldgA(32, regs);
    cp_wait0();
    __syncthreads();

    for (int kt = 0; kt < NKT; kt++) {
        const int buf = kt & 1;

        if (kt + 1 < NKT) {
            stsA(buf ^ 1, regs);
            cpB(buf ^ 1, (kt + 1) * 32);
            cp_commit();
        }
        if (kt + 2 < NKT) ldgA((kt + 2) * 32, regs);

        const char* sA = smem + buf * STAGE_BYTES;
        const char* sB = sA + PART_A;

#pragma unroll
        for (int ks = 0; ks < 4; ks++) {
            const int cb = ks * 32 + tig * 4;
            uint32_t a[2][4];
#pragma unroll
            for (int ms = 0; ms < 2; ms++) {
                const int r = wm + ms * 16 + g;
                a[ms][0] = *(const uint32_t*)(sA + r * APITCH + cb);
                a[ms][1] = *(const uint32_t*)(sA + (r + 8) * APITCH + cb);
                a[ms][2] = *(const uint32_t*)(sA + r * APITCH + cb + 16);
                a[ms][3] = *(const uint32_t*)(sA + (r + 8) * APITCH + cb + 16);
            }
            const char* bn = sB + (ks * 8 + tig) * BPITCH + (wn + g) * 4;
#pragma unroll
            for (int ns = 0; ns < 8; ns++) {
                uint32_t b0 = f2tf32(*(const float*)(bn + ns * 32));
                uint32_t b1 = f2tf32(*(const float*)(bn + 4 * BPITCH + ns * 32));
#pragma unroll
                for (int ms = 0; ms < 2; ms++)
                    mma16888(acc[ms][ns], a[ms], b0, b1);
            }
        }
        if (kt + 1 < NKT) cp_wait0();
        __syncthreads();
    }

#pragma unroll
    for (int ns = 0; ns < 8; ns++) {
        const int n = n0 + wn + ns * 8 + 2 * tig;
        float2 bb = *(const float2*)(bias + n);
#pragma unroll
        for (int ms = 0; ms < 2; ms++) {
            const int m = m0 + wm + ms * 16 + g;
            float2 o0, o1;
            o0.x = acc[ms][ns][0] + bb.x;
            o0.y = acc[ms][ns][1] + bb.y;
            o1.x = acc[ms][ns][2] + bb.x;
            o1.y = acc[ms][ns][3] + bb.y;
            *(float2*)(C + (size_t)m * U_DIM + n) = o0;
            *(float2*)(C + (size_t)(m + 8) * U_DIM + n) = o1;
        }
    }
}

// ---------------------------------------------------------------------------
__global__ void indrnn_gemm_naive(
    const float* __restrict__ A, const float* __restrict__ Bw,
    const float* __restrict__ bias, float* __restrict__ Cc,
    int M, int N, int K)
{
    int idx = blockIdx.x * blockDim.x + threadIdx.x;
    if (idx >= M * N) return;
    int m = idx / N, n = idx % N;
    float s = bias[n];
    for (int k = 0; k < K; k++) s = fmaf(A[(size_t)m * K + k], Bw[(size_t)k * N + n], s);
    Cc[idx] = s;
}

// ---------------------------------------------------------------------------
// Scan v3: float2 chains (2 per thread), depth-32 double-buffered ping-pong.
// 16384 threads x 32 float2 loads in flight = 4 MB chip-wide (round-9 MLP
// level) at half the per-byte instruction cost.
// ---------------------------------------------------------------------------
__global__ __launch_bounds__(64) void indrnn_scan2(
    float* __restrict__ out, const float* __restrict__ h0,
    const float* __restrict__ u, int B, int T, int U)
{
    const int U2 = U >> 1;
    int idx = blockIdx.x * blockDim.x + threadIdx.x;
    if (idx >= B * U2) return;
    int b = idx / U2;
    int j2 = idx - b * U2;

    float2 uu = ((const float2*)u)[j2];
    float ucx = fminf(fmaxf(uu.x, 0.0f), 1.0f);
    float ucy = fminf(fmaxf(uu.y, 0.0f), 1.0f);
    float2 h = ((const float2*)h0)[(size_t)b * U2 + j2];

    float2* p = (float2*)out + (size_t)b * T * U2 + j2;
    const size_t st = (size_t)U2;

#define SCAN_PROC32(buf, pw)                                    \
    do {                                                        \
        _Pragma("unroll")                                       \
        for (int i = 0; i < 32; i++) {                          \
            h.x = fmaxf(fmaf(h.x, ucx, (buf)[i].x), 0.0f);      \
            h.y = fmaxf(fmaf(h.y, ucy, (buf)[i].y), 0.0f);      \
            (pw)[i * st] = h;                                   \
        }                                                       \
    } while (0)

    if ((T & 63) == 0 && T >= 128) {
        float2 va[32], vb[32];
        const int NB = T / 32;             // even (T % 64 == 0)

#pragma unroll
        for (int i = 0; i < 32; i++) va[i] = __ldcs(p + i * st);

        for (int bI = 0; bI < NB; bI += 2) {
            float2* pa = p;                // batch bI
            float2* pb = p + 32 * st;      // batch bI+1
            if (bI + 1 < NB) {
#pragma unroll
                for (int i = 0; i < 32; i++) vb[i] = __ldcs(pb + i * st);
            }
            SCAN_PROC32(va, pa);
            if (bI + 1 >= NB) break;
            if (bI + 2 < NB) {
                float2* pc = p + 64 * st;  // batch bI+2
#pragma unroll
                for (int i = 0; i < 32; i++) va[i] = __ldcs(pc + i * st);
            }
            SCAN_PROC32(vb, pb);
            p += 64 * st;
        }
    } else {
        for (int t = 0; t < T; t++) {
            float2 v = __ldcs(p);
            h.x = fmaxf(fmaf(h.x, ucx, v.x), 0.0f);
            h.y = fmaxf(fmaf(h.y, ucy, v.y), 0.0f);
            *p = h;
            p += st;
        }
    }
#undef SCAN_PROC32
}

// Scalar fallback for odd U.
__global__ __launch_bounds__(128) void indrnn_scan1(
    float* __restrict__ out, const float* __restrict__ h0,
    const float* __restrict__ u, int B, int T, int U)
{
    int idx = blockIdx.x * blockDim.x + threadIdx.x;
    if (idx >= B * U) return;
    int b = idx / U;
    int j = idx - b * U;
    float uc = fminf(fmaxf(u[j], 0.0f), 1.0f);
    float h = h0[idx];
    float* p = out + (size_t)b * T * U + j;
    for (int t = 0; t < T; t++) {
        float v = __ldcg(p);
        h = fmaxf(fmaf(h, uc, v), 0.0f);
        *p = h;
        p += (size_t)U;
    }
}

// ---------------------------------------------------------------------------
extern "C" void kernel_launch(void* const* d_in, const int* in_sizes, int n_in,
                              void* d_out, int out_size)
{
    const float* x  = (const float*)d_in[0];
    const float* h0 = (const float*)d_in[1];
    const float* W  = (const float*)d_in[2];
    const float* u  = (const float*)d_in[3];
    const float* bb = (const float*)d_in[4];
    float* out = (float*)d_out;

    const int U = in_sizes[3];
    const int B = in_sizes[1] / U;
    const int D = in_sizes[2] / U;
    const int T = in_sizes[0] / (B * D);

    const int M = B * T;
    const int N = U;
    const int K = D;

    if (M == M_DIM && N == U_DIM && K == K_DIM) {
        cudaFuncSetAttribute(indrnn_gemm_tf32,
                             cudaFuncAttributeMaxDynamicSharedMemorySize, GEMM_SMEM);
        indrnn_gemm_tf32<<<dim3(N / 128, M / 128), 256, GEMM_SMEM>>>(x, W, bb, out);
    } else {
        int total = M * N;
        indrnn_gemm_naive<<<(total + 255) / 256, 256>>>(x, W, bb, out, M, N, K);
    }

    if ((U & 1) == 0) {
        int pairs = B * (U >> 1);
        indrnn_scan2<<<(pairs + 63) / 64, 64>>>(out, h0, u, B, T, U);
    } else {
        int chains = B * U;
        indrnn_scan1<<<(chains + 127) / 128, 128>>>(out, h0, u, B, T, U);
    }
}